// round 3
// baseline (speedup 1.0000x reference)
#include <cuda_runtime.h>
#include <math.h>

#define BATCH   16
#define N_PEP   128
#define M_PRO   2048
#define HEADS   8
#define DH      96
#define INNER   768
#define SCALE_F 0.10206207261596577f   /* 96^-0.5 */
#define NEG_F   -1000000.0f
#define EPS_F   1e-5f

#define BM 128
#define BN 128
#define BK 16
#define PADK 20   /* BK + 4, conflict-free fragment reads */

// ---------------- scratch (device globals; no allocations) ----------------
__device__ float g_q   [BATCH * N_PEP * INNER];
__device__ float g_k   [BATCH * M_PRO * INNER];
__device__ float g_vp  [BATCH * M_PRO * INNER];
__device__ float g_vq  [BATCH * N_PEP * INNER];
__device__ float g_cp  [BATCH * N_PEP * INNER];
__device__ float g_cq  [BATCH * M_PRO * INNER];
__device__ float g_y1  [BATCH * N_PEP * INNER];
__device__ float g_y2  [BATCH * M_PRO * INNER];

// ---------------- tf32 helpers ----------------
__device__ __forceinline__ unsigned f2tf(float x) {
    unsigned r;
    asm("cvt.rna.tf32.f32 %0, %1;" : "=r"(r) : "f"(x));
    return r;
}

__device__ __forceinline__ void mma_tf32(float* c, const unsigned* a,
                                         unsigned b0, unsigned b1) {
    asm volatile(
        "mma.sync.aligned.m16n8k8.row.col.f32.tf32.tf32.f32 "
        "{%0,%1,%2,%3}, {%4,%5,%6,%7}, {%8,%9}, {%0,%1,%2,%3};"
        : "+f"(c[0]), "+f"(c[1]), "+f"(c[2]), "+f"(c[3])
        : "r"(a[0]), "r"(a[1]), "r"(a[2]), "r"(a[3]), "r"(b0), "r"(b1));
}

// ---------------- 128x128x16 double-buffered tf32 GEMM tile ----------------
// TA: A stored (K, M) row-major, lda; else (M, K).
// TB: B stored (N, K) row-major, ldb; else (K, N).
// K % 16 == 0; M % 128 == 0 in all uses; N % 4 == 0.
template <bool TA, bool TB>
__device__ __forceinline__ void gemm_mma(const float* __restrict__ A,
                                         const float* __restrict__ Bm,
                                         float* __restrict__ C,
                                         int M, int N, int K,
                                         int lda, int ldb, int ldc,
                                         float alpha, int row0, int col0)
{
    __shared__ unsigned As[2][BM][PADK];   // [m][k] tf32 bits
    __shared__ unsigned Bs[2][BN][PADK];   // [n][k] tf32 bits

    const int tid  = threadIdx.x;
    const int lane = tid & 31;
    const int wid  = tid >> 5;
    const int wm   = (wid >> 1) * 32;
    const int wn   = (wid & 1) * 64;

    float acc[2][8][4];
#pragma unroll
    for (int i = 0; i < 2; i++)
#pragma unroll
        for (int j = 0; j < 8; j++)
#pragma unroll
            for (int t = 0; t < 4; t++) acc[i][j][t] = 0.0f;

    // staging registers
    float4 a4[2]; float a8[8];
    float4 b4[2];

    const int nTiles = K / BK;

    // ---- tile load: global -> regs ----
    auto load_regs = [&](int k0) {
        if (!TA) {
#pragma unroll
            for (int it = 0; it < 2; it++) {
                int idx = tid + it * 256;        // 0..511
                int m   = idx >> 2;              // 0..127
                int kk  = (idx & 3) * 4;
                a4[it] = make_float4(0.f, 0.f, 0.f, 0.f);
                if (row0 + m < M)
                    a4[it] = *(const float4*)&A[(long)(row0 + m) * lda + k0 + kk];
            }
        } else {
            int m  = tid & 127;
            int kb = (tid >> 7) * 8;
            bool ok = (row0 + m < M);
#pragma unroll
            for (int j = 0; j < 8; j++)
                a8[j] = ok ? A[(long)(k0 + kb + j) * lda + row0 + m] : 0.0f;
        }
        if (!TB) {
#pragma unroll
            for (int it = 0; it < 2; it++) {
                int idx = tid + it * 256;
                int kk  = idx >> 5;              // 0..15
                int n4  = (idx & 31) * 4;
                b4[it] = make_float4(0.f, 0.f, 0.f, 0.f);
                if (col0 + n4 < N)
                    b4[it] = *(const float4*)&Bm[(long)(k0 + kk) * ldb + col0 + n4];
            }
        } else {
#pragma unroll
            for (int it = 0; it < 2; it++) {
                int idx = tid + it * 256;
                int n   = idx >> 2;              // 0..127
                int kq  = (idx & 3) * 4;
                b4[it] = make_float4(0.f, 0.f, 0.f, 0.f);
                if (col0 + n < N)
                    b4[it] = *(const float4*)&Bm[(long)(col0 + n) * ldb + k0 + kq];
            }
        }
    };

    // ---- tile store: regs -> smem (with tf32 convert) ----
    auto store_smem = [&](int buf) {
        if (!TA) {
#pragma unroll
            for (int it = 0; it < 2; it++) {
                int idx = tid + it * 256;
                int m   = idx >> 2;
                int kk  = (idx & 3) * 4;
                unsigned* p = &As[buf][m][kk];
                p[0] = f2tf(a4[it].x); p[1] = f2tf(a4[it].y);
                p[2] = f2tf(a4[it].z); p[3] = f2tf(a4[it].w);
            }
        } else {
            int m  = tid & 127;
            int kb = (tid >> 7) * 8;
#pragma unroll
            for (int j = 0; j < 8; j++)
                As[buf][m][kb + j] = f2tf(a8[j]);
        }
        if (!TB) {
#pragma unroll
            for (int it = 0; it < 2; it++) {
                int idx = tid + it * 256;
                int kk  = idx >> 5;
                int n4  = (idx & 31) * 4;
                Bs[buf][n4 + 0][kk] = f2tf(b4[it].x);
                Bs[buf][n4 + 1][kk] = f2tf(b4[it].y);
                Bs[buf][n4 + 2][kk] = f2tf(b4[it].z);
                Bs[buf][n4 + 3][kk] = f2tf(b4[it].w);
            }
        } else {
#pragma unroll
            for (int it = 0; it < 2; it++) {
                int idx = tid + it * 256;
                int n   = idx >> 2;
                int kq  = (idx & 3) * 4;
                unsigned* p = &Bs[buf][n][kq];
                p[0] = f2tf(b4[it].x); p[1] = f2tf(b4[it].y);
                p[2] = f2tf(b4[it].z); p[3] = f2tf(b4[it].w);
            }
        }
    };

    load_regs(0);
    store_smem(0);
    __syncthreads();

    int buf = 0;
    const int ar = wm + (lane >> 2);
    const int ac = lane & 3;
    const int bnb = wn + (lane >> 2);

    for (int t = 0; t < nTiles; t++) {
        if (t + 1 < nTiles) load_regs((t + 1) * BK);

#pragma unroll
        for (int kc = 0; kc < BK; kc += 8) {
            unsigned af0[4], af1[4];
            af0[0] = As[buf][ar     ][kc + ac];
            af0[1] = As[buf][ar +  8][kc + ac];
            af0[2] = As[buf][ar     ][kc + ac + 4];
            af0[3] = As[buf][ar +  8][kc + ac + 4];
            af1[0] = As[buf][ar + 16][kc + ac];
            af1[1] = As[buf][ar + 24][kc + ac];
            af1[2] = As[buf][ar + 16][kc + ac + 4];
            af1[3] = As[buf][ar + 24][kc + ac + 4];
#pragma unroll
            for (int j = 0; j < 8; j++) {
                unsigned b0 = Bs[buf][bnb + j * 8][kc + ac];
                unsigned b1 = Bs[buf][bnb + j * 8][kc + ac + 4];
                mma_tf32(acc[0][j], af0, b0, b1);
                mma_tf32(acc[1][j], af1, b0, b1);
            }
        }

        if (t + 1 < nTiles) store_smem(buf ^ 1);
        __syncthreads();
        buf ^= 1;
    }

    // ---- epilogue (N % 4 == 0 -> paired stores are safe when c < N) ----
#pragma unroll
    for (int i = 0; i < 2; i++) {
#pragma unroll
        for (int j = 0; j < 8; j++) {
            int r = row0 + wm + i * 16 + (lane >> 2);
            int c = col0 + wn + j * 8 + (lane & 3) * 2;
            if (r < M && c < N) {
                float2 v0 = make_float2(alpha * acc[i][j][0], alpha * acc[i][j][1]);
                *(float2*)&C[(long)r * ldc + c] = v0;
            }
            if (r + 8 < M && c < N) {
                float2 v1 = make_float2(alpha * acc[i][j][2], alpha * acc[i][j][3]);
                *(float2*)&C[(long)(r + 8) * ldc + c] = v1;
            }
        }
    }
}

// ---------------- kernel wrappers ----------------
__global__ void __launch_bounds__(256)
k_gemm_nn(const float* __restrict__ A, const float* __restrict__ Bm,
          float* __restrict__ C, int M, int N, int K,
          int lda, int ldb, int ldc, float alpha)
{
    gemm_mma<false, false>(A, Bm, C, M, N, K, lda, ldb, ldc, alpha,
                           blockIdx.y * BM, blockIdx.x * BN);
}

__global__ void __launch_bounds__(256)
k_scores(const float* __restrict__ q, const float* __restrict__ kb,
         float* __restrict__ attn)
{
    int z = blockIdx.z;
    int b = z >> 3, h = z & 7;
    const float* A  = q  + (long)b * N_PEP * INNER + h * DH;
    const float* Bm = kb + (long)b * M_PRO * INNER + h * DH;
    float* C = attn + (long)z * N_PEP * M_PRO;
    gemm_mma<false, true>(A, Bm, C, N_PEP, M_PRO, DH,
                          INNER, INNER, M_PRO, SCALE_F,
                          blockIdx.y * BM, blockIdx.x * BN);
}

__global__ void __launch_bounds__(256)
k_ctxprot(const float* __restrict__ attn, const float* __restrict__ vprot,
          float* __restrict__ ctx)
{
    int z = blockIdx.z; int b = z >> 3, h = z & 7;
    const float* A  = attn  + (long)z * N_PEP * M_PRO;
    const float* Bm = vprot + (long)b * M_PRO * INNER + h * DH;
    float* C = ctx + (long)b * N_PEP * INNER + h * DH;
    gemm_mma<false, false>(A, Bm, C, N_PEP, DH, M_PRO,
                           M_PRO, INNER, INNER, 1.0f, 0, 0);
}

__global__ void __launch_bounds__(256)
k_ctxpep(const float* __restrict__ attn, const float* __restrict__ vpep,
         float* __restrict__ ctx)
{
    int z = blockIdx.z; int b = z >> 3, h = z & 7;
    const float* A  = attn + (long)z * N_PEP * M_PRO;   // (K=n, M=m) layout
    const float* Bm = vpep + (long)b * N_PEP * INNER + h * DH;
    float* C = ctx + (long)b * M_PRO * INNER + h * DH;
    gemm_mma<true, false>(A, Bm, C, M_PRO, DH, N_PEP,
                          M_PRO, INNER, INNER, 1.0f,
                          blockIdx.y * BM, 0);
}

// masked softmax over m, in-place on attn region of d_out
__global__ void __launch_bounds__(256)
k_softmax(float* __restrict__ attn, const int* __restrict__ pmask,
          const int* __restrict__ promask)
{
    int row = blockIdx.x;
    int n = row & (N_PEP - 1);
    int z = row / N_PEP;
    int b = z >> 3;
    float* p = attn + (long)row * M_PRO;
    const int row_valid = pmask[b * N_PEP + n];
    const int* pm = promask + b * M_PRO;
    const int tid = threadIdx.x;

    float vals[8];
    float mx = -INFINITY;
#pragma unroll
    for (int i = 0; i < 8; i++) {
        int c = tid + i * 256;
        float v = p[c];
        if (row_valid == 0 || pm[c] == 0) v = NEG_F;
        vals[i] = v;
        mx = fmaxf(mx, v);
    }
    __shared__ float red[256];
    red[tid] = mx; __syncthreads();
    for (int s = 128; s > 0; s >>= 1) {
        if (tid < s) red[tid] = fmaxf(red[tid], red[tid + s]);
        __syncthreads();
    }
    mx = red[0]; __syncthreads();

    float sum = 0.0f;
#pragma unroll
    for (int i = 0; i < 8; i++) { vals[i] = expf(vals[i] - mx); sum += vals[i]; }
    red[tid] = sum; __syncthreads();
    for (int s = 128; s > 0; s >>= 1) {
        if (tid < s) red[tid] += red[tid + s];
        __syncthreads();
    }
    float inv = 1.0f / red[0];
#pragma unroll
    for (int i = 0; i < 8; i++) p[tid + i * 256] = vals[i] * inv;
}

// out = LayerNorm(Y + bias + residual) * g + b
__global__ void __launch_bounds__(256)
k_ln(const float* __restrict__ Y, const float* __restrict__ bo,
     const float* __restrict__ resid, const float* __restrict__ g,
     const float* __restrict__ beta, float* __restrict__ out)
{
    int row = blockIdx.x;
    int tid = threadIdx.x;
    const float* y = Y + (long)row * INNER;
    const float* r = resid + (long)row * INNER;

    float x[3];
    float s = 0.0f;
#pragma unroll
    for (int i = 0; i < 3; i++) {
        int c = tid + i * 256;
        x[i] = y[c] + bo[c] + r[c];
        s += x[i];
    }
    __shared__ float red[256];
    red[tid] = s; __syncthreads();
    for (int st = 128; st > 0; st >>= 1) {
        if (tid < st) red[tid] += red[tid + st];
        __syncthreads();
    }
    float mu = red[0] * (1.0f / INNER); __syncthreads();

    float v = 0.0f;
#pragma unroll
    for (int i = 0; i < 3; i++) { float d = x[i] - mu; v += d * d; }
    red[tid] = v; __syncthreads();
    for (int st = 128; st > 0; st >>= 1) {
        if (tid < st) red[tid] += red[tid + st];
        __syncthreads();
    }
    float rstd = rsqrtf(red[0] * (1.0f / INNER) + EPS_F);
#pragma unroll
    for (int i = 0; i < 3; i++) {
        int c = tid + i * 256;
        out[(long)row * INNER + c] = (x[i] - mu) * rstd * g[c] + beta[c];
    }
}

// ---------------- launch ----------------
extern "C" void kernel_launch(void* const* d_in, const int* in_sizes, int n_in,
                              void* d_out, int out_size)
{
    const float* peptide = (const float*)d_in[0];
    const float* protein = (const float*)d_in[1];
    const int*   pmask   = (const int*)  d_in[2];
    const int*   promask = (const int*)  d_in[3];
    const float* Wq      = (const float*)d_in[4];
    const float* Wk      = (const float*)d_in[5];
    const float* Wvp     = (const float*)d_in[6];
    const float* Wvq     = (const float*)d_in[7];
    const float* Wop     = (const float*)d_in[8];
    const float* bop     = (const float*)d_in[9];
    const float* Woq     = (const float*)d_in[10];
    const float* boq     = (const float*)d_in[11];
    const float* lng     = (const float*)d_in[12];
    const float* lnb     = (const float*)d_in[13];

    float* out = (float*)d_out;
    float* out_prot = out;                                   // (16,128,768)
    float* out_pep  = out + (long)BATCH * N_PEP * INNER;     // (16,2048,768)
    float* attn     = out_pep + (long)BATCH * M_PRO * INNER; // (16,8,128,2048)

    float *q, *k, *vp, *vq, *cp, *cq, *y1, *y2;
    cudaGetSymbolAddress((void**)&q,  g_q);
    cudaGetSymbolAddress((void**)&k,  g_k);
    cudaGetSymbolAddress((void**)&vp, g_vp);
    cudaGetSymbolAddress((void**)&vq, g_vq);
    cudaGetSymbolAddress((void**)&cp, g_cp);
    cudaGetSymbolAddress((void**)&cq, g_cq);
    cudaGetSymbolAddress((void**)&y1, g_y1);
    cudaGetSymbolAddress((void**)&y2, g_y2);

    const dim3 blk(256);

    // projections
    k_gemm_nn<<<dim3(6, 16),  blk>>>(peptide, Wq,  q,  BATCH * N_PEP, INNER, INNER, INNER, INNER, INNER, 1.0f);
    k_gemm_nn<<<dim3(6, 16),  blk>>>(peptide, Wvq, vq, BATCH * N_PEP, INNER, INNER, INNER, INNER, INNER, 1.0f);
    k_gemm_nn<<<dim3(6, 256), blk>>>(protein, Wk,  k,  BATCH * M_PRO, INNER, INNER, INNER, INNER, INNER, 1.0f);
    k_gemm_nn<<<dim3(6, 256), blk>>>(protein, Wvp, vp, BATCH * M_PRO, INNER, INNER, INNER, INNER, INNER, 1.0f);

    // attention scores + softmax (attn lives in d_out)
    k_scores <<<dim3(16, 1, BATCH * HEADS), blk>>>(q, k, attn);
    k_softmax<<<BATCH * HEADS * N_PEP, 256>>>(attn, pmask, promask);

    // context
    k_ctxprot<<<dim3(1, 1,  BATCH * HEADS), blk>>>(attn, vp, cp);
    k_ctxpep <<<dim3(1, 16, BATCH * HEADS), blk>>>(attn, vq, cq);

    // output projections
    k_gemm_nn<<<dim3(6, 16),  blk>>>(cp, Wop, y1, BATCH * N_PEP, INNER, INNER, INNER, INNER, INNER, 1.0f);
    k_gemm_nn<<<dim3(6, 256), blk>>>(cq, Woq, y2, BATCH * M_PRO, INNER, INNER, INNER, INNER, INNER, 1.0f);

    // bias + residual + layernorm
    k_ln<<<BATCH * N_PEP, 256>>>(y1, bop, peptide, lng, lnb, out_prot);
    k_ln<<<BATCH * M_PRO, 256>>>(y2, boq, protein, lng, lnb, out_pep);
}

// round 4
// speedup vs baseline: 1.5374x; 1.5374x over previous
#include <cuda_runtime.h>
#include <math.h>

#define BATCH   16
#define N_PEP   128
#define M_PRO   2048
#define HEADS   8
#define DH      96
#define INNER   768
#define SCALE_F 0.10206207261596577f   /* 96^-0.5 */
#define NEG_F   -1000000.0f
#define EPS_F   1e-5f

#define BM 128
#define BN 128
#define BK 32

// ---------------- scratch (device globals; no allocations) ----------------
__device__ float g_q   [BATCH * N_PEP * INNER];
__device__ float g_k   [BATCH * M_PRO * INNER];
__device__ float g_vp  [BATCH * M_PRO * INNER];
__device__ float g_vq  [BATCH * N_PEP * INNER];
__device__ float g_cp  [BATCH * N_PEP * INNER];
__device__ float g_cq  [BATCH * M_PRO * INNER];
__device__ float g_y1  [BATCH * N_PEP * INNER];
__device__ float g_y2  [BATCH * M_PRO * INNER];

// ---------------- tf32 helpers ----------------
__device__ __forceinline__ unsigned f2tf(float x) {
    unsigned r;
    asm("cvt.rna.tf32.f32 %0, %1;" : "=r"(r) : "f"(x));
    return r;
}

__device__ __forceinline__ void mma_tf32(float* c, const unsigned* a,
                                         unsigned b0, unsigned b1) {
    asm volatile(
        "mma.sync.aligned.m16n8k8.row.col.f32.tf32.tf32.f32 "
        "{%0,%1,%2,%3}, {%4,%5,%6,%7}, {%8,%9}, {%0,%1,%2,%3};"
        : "+f"(c[0]), "+f"(c[1]), "+f"(c[2]), "+f"(c[3])
        : "r"(a[0]), "r"(a[1]), "r"(a[2]), "r"(a[3]), "r"(b0), "r"(b1));
}

// smem layouts (words). All accesses conflict-free (stores vectorized,
// fragment reads hit 32 distinct banks):
//   TA=0:  As[m][k]  stride 36    TA=1:  As[k][m]  stride 136
//   TB=0:  Bs[k][n]  stride 136   TB=1:  Bs[n][k]  stride 36
#define AS_MK(m, k) sA[(m) * 36 + (k)]
#define AS_KM(k, m) sA[(k) * 136 + (m)]
#define BS_KN(k, n) sB[(k) * 136 + (n)]
#define BS_NK(n, k) sB[(n) * 36 + (k)]

// ---------------- 128x128x32 tf32 tensor GEMM tile ----------------
// TA: A stored (K, M) row-major, lda; else (M, K).
// TB: B stored (N, K) row-major, ldb; else (K, N).
// K % 32 == 0; M % 128 == 0 in all uses; N % 4 == 0.
template <bool TA, bool TB>
__device__ __forceinline__ void gemm_mma(const float* __restrict__ A,
                                         const float* __restrict__ Bm,
                                         float* __restrict__ C,
                                         int M, int N, int K,
                                         int lda, int ldb, int ldc,
                                         float alpha, int row0, int col0)
{
    __shared__ unsigned sA[4608];   // max(128*36, 32*136)
    __shared__ unsigned sB[4608];   // max(32*136, 128*36)

    const int tid  = threadIdx.x;
    const int lane = tid & 31;
    const int wid  = tid >> 5;
    const int wm   = (wid >> 1) * 32;
    const int wn   = (wid & 1) * 64;

    float acc[2][8][4];
#pragma unroll
    for (int i = 0; i < 2; i++)
#pragma unroll
        for (int j = 0; j < 8; j++)
#pragma unroll
            for (int t = 0; t < 4; t++) acc[i][j][t] = 0.0f;

    float4 a4[4], b4[4];            // staging registers

    const int nTiles = K / BK;

    // ---- global -> regs ----
    auto load_regs = [&](int k0) {
        if (!TA) {
#pragma unroll
            for (int it = 0; it < 4; it++) {
                int idx = tid + it * 256;          // 0..1023
                int m   = idx >> 3;                // 0..127
                int kk  = (idx & 7) * 4;           // 0..28
                a4[it] = *(const float4*)&A[(long)(row0 + m) * lda + k0 + kk];
            }
        } else {
#pragma unroll
            for (int it = 0; it < 4; it++) {
                int idx = tid + it * 256;
                int kk  = idx >> 5;                // 0..31
                int m4  = (idx & 31) * 4;          // 0..124
                a4[it] = *(const float4*)&A[(long)(k0 + kk) * lda + row0 + m4];
            }
        }
        if (!TB) {
#pragma unroll
            for (int it = 0; it < 4; it++) {
                int idx = tid + it * 256;
                int kk  = idx >> 5;                // 0..31
                int n4  = (idx & 31) * 4;          // 0..124
                b4[it] = make_float4(0.f, 0.f, 0.f, 0.f);
                if (col0 + n4 < N)
                    b4[it] = *(const float4*)&Bm[(long)(k0 + kk) * ldb + col0 + n4];
            }
        } else {
#pragma unroll
            for (int it = 0; it < 4; it++) {
                int idx = tid + it * 256;
                int n   = idx >> 3;                // 0..127
                int kq  = (idx & 7) * 4;           // 0..28
                b4[it] = make_float4(0.f, 0.f, 0.f, 0.f);
                if (col0 + n < N)
                    b4[it] = *(const float4*)&Bm[(long)(col0 + n) * ldb + k0 + kq];
            }
        }
    };

    // ---- regs -> smem (tf32 convert here, outside the MMA loop) ----
    auto store_smem = [&]() {
        if (!TA) {
#pragma unroll
            for (int it = 0; it < 4; it++) {
                int idx = tid + it * 256;
                int m   = idx >> 3;
                int kk  = (idx & 7) * 4;
                uint4 u = make_uint4(f2tf(a4[it].x), f2tf(a4[it].y),
                                     f2tf(a4[it].z), f2tf(a4[it].w));
                *(uint4*)&AS_MK(m, kk) = u;
            }
        } else {
#pragma unroll
            for (int it = 0; it < 4; it++) {
                int idx = tid + it * 256;
                int kk  = idx >> 5;
                int m4  = (idx & 31) * 4;
                uint4 u = make_uint4(f2tf(a4[it].x), f2tf(a4[it].y),
                                     f2tf(a4[it].z), f2tf(a4[it].w));
                *(uint4*)&AS_KM(kk, m4) = u;
            }
        }
        if (!TB) {
#pragma unroll
            for (int it = 0; it < 4; it++) {
                int idx = tid + it * 256;
                int kk  = idx >> 5;
                int n4  = (idx & 31) * 4;
                uint4 u = make_uint4(f2tf(b4[it].x), f2tf(b4[it].y),
                                     f2tf(b4[it].z), f2tf(b4[it].w));
                *(uint4*)&BS_KN(kk, n4) = u;
            }
        } else {
#pragma unroll
            for (int it = 0; it < 4; it++) {
                int idx = tid + it * 256;
                int n   = idx >> 3;
                int kq  = (idx & 7) * 4;
                uint4 u = make_uint4(f2tf(b4[it].x), f2tf(b4[it].y),
                                     f2tf(b4[it].z), f2tf(b4[it].w));
                *(uint4*)&BS_NK(n, kq) = u;
            }
        }
    };

    load_regs(0);

    const int arq = lane >> 2;      // 0..7
    const int ac  = lane & 3;       // 0..3

    for (int t = 0; t < nTiles; t++) {
        store_smem();
        __syncthreads();
        if (t + 1 < nTiles) load_regs((t + 1) * BK);   // overlap LDG with MMA

#pragma unroll
        for (int kc = 0; kc < BK; kc += 8) {
            unsigned af0[4], af1[4];
            if (!TA) {
                af0[0] = AS_MK(wm + arq,      kc + ac);
                af0[1] = AS_MK(wm + arq + 8,  kc + ac);
                af0[2] = AS_MK(wm + arq,      kc + ac + 4);
                af0[3] = AS_MK(wm + arq + 8,  kc + ac + 4);
                af1[0] = AS_MK(wm + arq + 16, kc + ac);
                af1[1] = AS_MK(wm + arq + 24, kc + ac);
                af1[2] = AS_MK(wm + arq + 16, kc + ac + 4);
                af1[3] = AS_MK(wm + arq + 24, kc + ac + 4);
            } else {
                af0[0] = AS_KM(kc + ac,     wm + arq);
                af0[1] = AS_KM(kc + ac,     wm + arq + 8);
                af0[2] = AS_KM(kc + ac + 4, wm + arq);
                af0[3] = AS_KM(kc + ac + 4, wm + arq + 8);
                af1[0] = AS_KM(kc + ac,     wm + arq + 16);
                af1[1] = AS_KM(kc + ac,     wm + arq + 24);
                af1[2] = AS_KM(kc + ac + 4, wm + arq + 16);
                af1[3] = AS_KM(kc + ac + 4, wm + arq + 24);
            }
#pragma unroll
            for (int j = 0; j < 8; j++) {
                const int bn = wn + j * 8 + arq;
                unsigned b0, b1;
                if (!TB) {
                    b0 = BS_KN(kc + ac,     bn);
                    b1 = BS_KN(kc + ac + 4, bn);
                } else {
                    b0 = BS_NK(bn, kc + ac);
                    b1 = BS_NK(bn, kc + ac + 4);
                }
                mma_tf32(acc[0][j], af0, b0, b1);
                mma_tf32(acc[1][j], af1, b0, b1);
            }
        }
        __syncthreads();
    }

    // ---- epilogue ----
#pragma unroll
    for (int i = 0; i < 2; i++) {
#pragma unroll
        for (int j = 0; j < 8; j++) {
            int r = row0 + wm + i * 16 + arq;
            int c = col0 + wn + j * 8 + ac * 2;
            if (c < N) {
                *(float2*)&C[(long)r * ldc + c] =
                    make_float2(alpha * acc[i][j][0], alpha * acc[i][j][1]);
                *(float2*)&C[(long)(r + 8) * ldc + c] =
                    make_float2(alpha * acc[i][j][2], alpha * acc[i][j][3]);
            }
        }
    }
}

// ---------------- kernel wrappers ----------------
__global__ void __launch_bounds__(256)
k_gemm_nn(const float* __restrict__ A, const float* __restrict__ Bm,
          float* __restrict__ C, int M, int N, int K,
          int lda, int ldb, int ldc, float alpha)
{
    gemm_mma<false, false>(A, Bm, C, M, N, K, lda, ldb, ldc, alpha,
                           blockIdx.y * BM, blockIdx.x * BN);
}

__global__ void __launch_bounds__(256)
k_scores(const float* __restrict__ q, const float* __restrict__ kb,
         float* __restrict__ attn)
{
    int z = blockIdx.z;
    int b = z >> 3, h = z & 7;
    const float* A  = q  + (long)b * N_PEP * INNER + h * DH;
    const float* Bm = kb + (long)b * M_PRO * INNER + h * DH;
    float* C = attn + (long)z * N_PEP * M_PRO;
    gemm_mma<false, true>(A, Bm, C, N_PEP, M_PRO, DH,
                          INNER, INNER, M_PRO, SCALE_F,
                          blockIdx.y * BM, blockIdx.x * BN);
}

__global__ void __launch_bounds__(256)
k_ctxprot(const float* __restrict__ attn, const float* __restrict__ vprot,
          float* __restrict__ ctx)
{
    int z = blockIdx.z; int b = z >> 3, h = z & 7;
    const float* A  = attn  + (long)z * N_PEP * M_PRO;
    const float* Bm = vprot + (long)b * M_PRO * INNER + h * DH;
    float* C = ctx + (long)b * N_PEP * INNER + h * DH;
    gemm_mma<false, false>(A, Bm, C, N_PEP, DH, M_PRO,
                           M_PRO, INNER, INNER, 1.0f, 0, 0);
}

__global__ void __launch_bounds__(256)
k_ctxpep(const float* __restrict__ attn, const float* __restrict__ vpep,
         float* __restrict__ ctx)
{
    int z = blockIdx.z; int b = z >> 3, h = z & 7;
    const float* A  = attn + (long)z * N_PEP * M_PRO;   // (K=n, M=m) layout
    const float* Bm = vpep + (long)b * N_PEP * INNER + h * DH;
    float* C = ctx + (long)b * M_PRO * INNER + h * DH;
    gemm_mma<true, false>(A, Bm, C, M_PRO, DH, N_PEP,
                          M_PRO, INNER, INNER, 1.0f,
                          blockIdx.y * BM, 0);
}

// masked softmax over m, in-place on attn region of d_out
__global__ void __launch_bounds__(256)
k_softmax(float* __restrict__ attn, const int* __restrict__ pmask,
          const int* __restrict__ promask)
{
    int row = blockIdx.x;
    int n = row & (N_PEP - 1);
    int z = row / N_PEP;
    int b = z >> 3;
    float* p = attn + (long)row * M_PRO;
    const int row_valid = pmask[b * N_PEP + n];
    const int* pm = promask + b * M_PRO;
    const int tid = threadIdx.x;

    float vals[8];
    float mx = -INFINITY;
#pragma unroll
    for (int i = 0; i < 8; i++) {
        int c = tid + i * 256;
        float v = p[c];
        if (row_valid == 0 || pm[c] == 0) v = NEG_F;
        vals[i] = v;
        mx = fmaxf(mx, v);
    }
    __shared__ float red[256];
    red[tid] = mx; __syncthreads();
    for (int s = 128; s > 0; s >>= 1) {
        if (tid < s) red[tid] = fmaxf(red[tid], red[tid + s]);
        __syncthreads();
    }
    mx = red[0]; __syncthreads();

    float sum = 0.0f;
#pragma unroll
    for (int i = 0; i < 8; i++) { vals[i] = expf(vals[i] - mx); sum += vals[i]; }
    red[tid] = sum; __syncthreads();
    for (int s = 128; s > 0; s >>= 1) {
        if (tid < s) red[tid] += red[tid + s];
        __syncthreads();
    }
    float inv = 1.0f / red[0];
#pragma unroll
    for (int i = 0; i < 8; i++) p[tid + i * 256] = vals[i] * inv;
}

// out = LayerNorm(Y + bias + residual) * g + b
__global__ void __launch_bounds__(256)
k_ln(const float* __restrict__ Y, const float* __restrict__ bo,
     const float* __restrict__ resid, const float* __restrict__ g,
     const float* __restrict__ beta, float* __restrict__ out)
{
    int row = blockIdx.x;
    int tid = threadIdx.x;
    const float* y = Y + (long)row * INNER;
    const float* r = resid + (long)row * INNER;

    float x[3];
    float s = 0.0f;
#pragma unroll
    for (int i = 0; i < 3; i++) {
        int c = tid + i * 256;
        x[i] = y[c] + bo[c] + r[c];
        s += x[i];
    }
    __shared__ float red[256];
    red[tid] = s; __syncthreads();
    for (int st = 128; st > 0; st >>= 1) {
        if (tid < st) red[tid] += red[tid + st];
        __syncthreads();
    }
    float mu = red[0] * (1.0f / INNER); __syncthreads();

    float v = 0.0f;
#pragma unroll
    for (int i = 0; i < 3; i++) { float d = x[i] - mu; v += d * d; }
    red[tid] = v; __syncthreads();
    for (int st = 128; st > 0; st >>= 1) {
        if (tid < st) red[tid] += red[tid + st];
        __syncthreads();
    }
    float rstd = rsqrtf(red[0] * (1.0f / INNER) + EPS_F);
#pragma unroll
    for (int i = 0; i < 3; i++) {
        int c = tid + i * 256;
        out[(long)row * INNER + c] = (x[i] - mu) * rstd * g[c] + beta[c];
    }
}

// ---------------- launch ----------------
extern "C" void kernel_launch(void* const* d_in, const int* in_sizes, int n_in,
                              void* d_out, int out_size)
{
    const float* peptide = (const float*)d_in[0];
    const float* protein = (const float*)d_in[1];
    const int*   pmask   = (const int*)  d_in[2];
    const int*   promask = (const int*)  d_in[3];
    const float* Wq      = (const float*)d_in[4];
    const float* Wk      = (const float*)d_in[5];
    const float* Wvp     = (const float*)d_in[6];
    const float* Wvq     = (const float*)d_in[7];
    const float* Wop     = (const float*)d_in[8];
    const float* bop     = (const float*)d_in[9];
    const float* Woq     = (const float*)d_in[10];
    const float* boq     = (const float*)d_in[11];
    const float* lng     = (const float*)d_in[12];
    const float* lnb     = (const float*)d_in[13];

    float* out = (float*)d_out;
    float* out_prot = out;                                   // (16,128,768)
    float* out_pep  = out + (long)BATCH * N_PEP * INNER;     // (16,2048,768)
    float* attn     = out_pep + (long)BATCH * M_PRO * INNER; // (16,8,128,2048)

    float *q, *k, *vp, *vq, *cp, *cq, *y1, *y2;
    cudaGetSymbolAddress((void**)&q,  g_q);
    cudaGetSymbolAddress((void**)&k,  g_k);
    cudaGetSymbolAddress((void**)&vp, g_vp);
    cudaGetSymbolAddress((void**)&vq, g_vq);
    cudaGetSymbolAddress((void**)&cp, g_cp);
    cudaGetSymbolAddress((void**)&cq, g_cq);
    cudaGetSymbolAddress((void**)&y1, g_y1);
    cudaGetSymbolAddress((void**)&y2, g_y2);

    const dim3 blk(256);

    // projections
    k_gemm_nn<<<dim3(6, 16),  blk>>>(peptide, Wq,  q,  BATCH * N_PEP, INNER, INNER, INNER, INNER, INNER, 1.0f);
    k_gemm_nn<<<dim3(6, 16),  blk>>>(peptide, Wvq, vq, BATCH * N_PEP, INNER, INNER, INNER, INNER, INNER, 1.0f);
    k_gemm_nn<<<dim3(6, 256), blk>>>(protein, Wk,  k,  BATCH * M_PRO, INNER, INNER, INNER, INNER, INNER, 1.0f);
    k_gemm_nn<<<dim3(6, 256), blk>>>(protein, Wvp, vp, BATCH * M_PRO, INNER, INNER, INNER, INNER, INNER, 1.0f);

    // attention scores + softmax (attn lives in d_out)
    k_scores <<<dim3(16, 1, BATCH * HEADS), blk>>>(q, k, attn);
    k_softmax<<<BATCH * HEADS * N_PEP, 256>>>(attn, pmask, promask);

    // context
    k_ctxprot<<<dim3(1, 1,  BATCH * HEADS), blk>>>(attn, vp, cp);
    k_ctxpep <<<dim3(1, 16, BATCH * HEADS), blk>>>(attn, vq, cq);

    // output projections
    k_gemm_nn<<<dim3(6, 16),  blk>>>(cp, Wop, y1, BATCH * N_PEP, INNER, INNER, INNER, INNER, INNER, 1.0f);
    k_gemm_nn<<<dim3(6, 256), blk>>>(cq, Woq, y2, BATCH * M_PRO, INNER, INNER, INNER, INNER, INNER, 1.0f);

    // bias + residual + layernorm
    k_ln<<<BATCH * N_PEP, 256>>>(y1, bop, peptide, lng, lnb, out_prot);
    k_ln<<<BATCH * M_PRO, 256>>>(y2, boq, protein, lng, lnb, out_pep);
}

// round 6
// speedup vs baseline: 1.5625x; 1.0163x over previous
#include <cuda_runtime.h>
#include <math.h>

#define BATCH   16
#define N_PEP   128
#define M_PRO   2048
#define HEADS   8
#define DH      96
#define INNER   768
#define SCALE_F 0.10206207261596577f   /* 96^-0.5 */
#define NEG_F   -1000000.0f
#define EPS_F   1e-5f

#define BM 128
#define BN 128
#define BK 16
#define TILE_W 2048        /* words per operand tile (128x16 or 16x128) */

// ---------------- scratch (device globals; no allocations) ----------------
__device__ float g_q   [BATCH * N_PEP * INNER];
__device__ float g_k   [BATCH * M_PRO * INNER];
__device__ float g_vp  [BATCH * M_PRO * INNER];
__device__ float g_vq  [BATCH * N_PEP * INNER];
__device__ float g_cp  [BATCH * N_PEP * INNER];
__device__ float g_cq  [BATCH * M_PRO * INNER];
__device__ float g_y1  [BATCH * N_PEP * INNER];
__device__ float g_y2  [BATCH * M_PRO * INNER];

// ---------------- helpers ----------------
__device__ __forceinline__ unsigned f2tf(float x) {
    unsigned r;
    asm("cvt.rna.tf32.f32 %0, %1;" : "=r"(r) : "f"(x));
    return r;
}
__device__ __forceinline__ unsigned cvtw(unsigned w) {
    return f2tf(__uint_as_float(w));
}

__device__ __forceinline__ void mma_tf32(float* c, const unsigned* a,
                                         unsigned b0, unsigned b1) {
    asm volatile(
        "mma.sync.aligned.m16n8k8.row.col.f32.tf32.tf32.f32 "
        "{%0,%1,%2,%3}, {%4,%5,%6,%7}, {%8,%9}, {%0,%1,%2,%3};"
        : "+f"(c[0]), "+f"(c[1]), "+f"(c[2]), "+f"(c[3])
        : "r"(a[0]), "r"(a[1]), "r"(a[2]), "r"(a[3]), "r"(b0), "r"(b1));
}

__device__ __forceinline__ void cpasync16(unsigned* dst, const float* src, bool pred) {
    unsigned sa = (unsigned)__cvta_generic_to_shared(dst);
    int sz = pred ? 16 : 0;
    asm volatile("cp.async.cg.shared.global [%0], [%1], 16, %2;\n"
                 :: "r"(sa), "l"(src), "r"(sz));
}
#define CP_COMMIT() asm volatile("cp.async.commit_group;\n" ::)
#define CP_WAIT1()  asm volatile("cp.async.wait_group 1;\n" ::)
#define CP_WAIT0()  asm volatile("cp.async.wait_group 0;\n" ::)

// swizzled word layouts, zero padding, all accesses conflict-free:
//   16-word rows (A[m][k], B[n][k]):   r*16  + (c ^ (((r>>1)&3)*4))
//   128-word rows (A[k][m], B[k][n]):  r*128 + (c ^ ((r&7)*8))
#define SW16(r, c)  ((r) * 16  + ((c) ^ ((((r) >> 1) & 3) * 4)))
#define SW128(r, c) ((r) * 128 + ((c) ^ (((r) & 7) * 8)))

// ---------------- 128x128x16 double-buffered tf32 GEMM tile ----------------
// TA: A stored (K, M) row-major, lda; else (M, K).
// TB: B stored (N, K) row-major, ldb; else (K, N).
// K % 16 == 0; M covered exactly by grid; N % 4 == 0.
template <bool TA, bool TB>
__device__ __forceinline__ void gemm_mma(const float* __restrict__ A,
                                         const float* __restrict__ Bm,
                                         float* __restrict__ C,
                                         int M, int N, int K,
                                         int lda, int ldb, int ldc,
                                         float alpha, int row0, int col0)
{
    __shared__ unsigned sAb[2][TILE_W];
    __shared__ unsigned sBb[2][TILE_W];

    const int tid  = threadIdx.x;
    const int lane = tid & 31;
    const int wid  = tid >> 5;
    const int wm   = (wid >> 1) * 32;
    const int wn   = (wid & 1) * 64;

    float acc[2][8][4];
#pragma unroll
    for (int i = 0; i < 2; i++)
#pragma unroll
        for (int j = 0; j < 8; j++)
#pragma unroll
            for (int t = 0; t < 4; t++) acc[i][j][t] = 0.0f;

    const int nTiles = K / BK;

    // ---- async copy one k-tile into buffer `buf` ----
    auto issue = [&](int buf, int k0) {
        unsigned* sA = sAb[buf];
        unsigned* sB = sBb[buf];
#pragma unroll
        for (int it = 0; it < 2; it++) {
            int idx = tid + it * 256;          // 0..511
            if (!TA) {
                int m  = idx >> 2;             // 0..127
                int kk = (idx & 3) * 4;        // 0,4,8,12
                cpasync16(&sA[SW16(m, kk)],
                          &A[(long)(row0 + m) * lda + k0 + kk], true);
            } else {
                int kk = idx >> 5;             // 0..15
                int m4 = (idx & 31) * 4;       // 0..124
                cpasync16(&sA[SW128(kk, m4)],
                          &A[(long)(k0 + kk) * lda + row0 + m4], true);
            }
        }
#pragma unroll
        for (int it = 0; it < 2; it++) {
            int idx = tid + it * 256;
            if (!TB) {
                int kk = idx >> 5;
                int n4 = (idx & 31) * 4;
                cpasync16(&sB[SW128(kk, n4)],
                          &Bm[(long)(k0 + kk) * ldb + col0 + n4],
                          col0 + n4 < N);
            } else {
                int n  = idx >> 2;
                int kq = (idx & 3) * 4;
                cpasync16(&sB[SW16(n, kq)],
                          &Bm[(long)(col0 + n) * ldb + k0 + kq],
                          col0 + n < N);
            }
        }
        CP_COMMIT();
    };

    // ---- in-place fp32 -> tf32 (round-to-nearest) over one buffer ----
    auto convert = [&](int buf) {
        unsigned* sA = sAb[buf];
        unsigned* sB = sBb[buf];
#pragma unroll
        for (int it = 0; it < 2; it++) {
            int idx = tid + it * 256;
            unsigned* p;
            if (!TA) { int m = idx >> 2, kk = (idx & 3) * 4;  p = &sA[SW16(m, kk)]; }
            else     { int kk = idx >> 5, m4 = (idx & 31) * 4; p = &sA[SW128(kk, m4)]; }
            uint4 u = *(uint4*)p;
            u.x = cvtw(u.x); u.y = cvtw(u.y); u.z = cvtw(u.z); u.w = cvtw(u.w);
            *(uint4*)p = u;
        }
#pragma unroll
        for (int it = 0; it < 2; it++) {
            int idx = tid + it * 256;
            unsigned* p;
            if (!TB) { int kk = idx >> 5, n4 = (idx & 31) * 4; p = &sB[SW128(kk, n4)]; }
            else     { int n = idx >> 2, kq = (idx & 3) * 4;   p = &sB[SW16(n, kq)]; }
            uint4 u = *(uint4*)p;
            u.x = cvtw(u.x); u.y = cvtw(u.y); u.z = cvtw(u.z); u.w = cvtw(u.w);
            *(uint4*)p = u;
        }
    };

    const int arq = lane >> 2;      // 0..7
    const int ac  = lane & 3;       // 0..3

    issue(0, 0);

    for (int t = 0; t < nTiles; t++) {
        const int buf = t & 1;
        unsigned* sA = sAb[buf];
        unsigned* sB = sBb[buf];

        if (t + 1 < nTiles) {
            issue(buf ^ 1, (t + 1) * BK);
            CP_WAIT1();                 // tile t complete, t+1 in flight
        } else {
            CP_WAIT0();
        }
        __syncthreads();
        convert(buf);
        __syncthreads();

#pragma unroll
        for (int kc = 0; kc < BK; kc += 8) {
            unsigned af0[4], af1[4];
            if (!TA) {
                af0[0] = sA[SW16(wm + arq,      kc + ac)];
                af0[1] = sA[SW16(wm + arq + 8,  kc + ac)];
                af0[2] = sA[SW16(wm + arq,      kc + ac + 4)];
                af0[3] = sA[SW16(wm + arq + 8,  kc + ac + 4)];
                af1[0] = sA[SW16(wm + arq + 16, kc + ac)];
                af1[1] = sA[SW16(wm + arq + 24, kc + ac)];
                af1[2] = sA[SW16(wm + arq + 16, kc + ac + 4)];
                af1[3] = sA[SW16(wm + arq + 24, kc + ac + 4)];
            } else {
                af0[0] = sA[SW128(kc + ac,     wm + arq)];
                af0[1] = sA[SW128(kc + ac,     wm + arq + 8)];
                af0[2] = sA[SW128(kc + ac + 4, wm + arq)];
                af0[3] = sA[SW128(kc + ac + 4, wm + arq + 8)];
                af1[0] = sA[SW128(kc + ac,     wm + arq + 16)];
                af1[1] = sA[SW128(kc + ac,     wm + arq + 24)];
                af1[2] = sA[SW128(kc + ac + 4, wm + arq + 16)];
                af1[3] = sA[SW128(kc + ac + 4, wm + arq + 24)];
            }
#pragma unroll
            for (int j = 0; j < 8; j++) {
                const int bn = wn + j * 8 + arq;
                unsigned b0, b1;
                if (!TB) {
                    b0 = sB[SW128(kc + ac,     bn)];
                    b1 = sB[SW128(kc + ac + 4, bn)];
                } else {
                    b0 = sB[SW16(bn, kc + ac)];
                    b1 = sB[SW16(bn, kc + ac + 4)];
                }
                mma_tf32(acc[0][j], af0, b0, b1);
                mma_tf32(acc[1][j], af1, b0, b1);
            }
        }
        __syncthreads();
    }

    // ---- epilogue ----
#pragma unroll
    for (int i = 0; i < 2; i++) {
#pragma unroll
        for (int j = 0; j < 8; j++) {
            int r = row0 + wm + i * 16 + arq;
            int c = col0 + wn + j * 8 + ac * 2;
            if (c < N) {
                *(float2*)&C[(long)r * ldc + c] =
                    make_float2(alpha * acc[i][j][0], alpha * acc[i][j][1]);
                *(float2*)&C[(long)(r + 8) * ldc + c] =
                    make_float2(alpha * acc[i][j][2], alpha * acc[i][j][3]);
            }
        }
    }
}

// ---------------- kernel wrappers ----------------
__global__ void __launch_bounds__(256, 2)
k_gemm_nn(const float* __restrict__ A, const float* __restrict__ Bm,
          float* __restrict__ C, int M, int N, int K,
          int lda, int ldb, int ldc, float alpha)
{
    gemm_mma<false, false>(A, Bm, C, M, N, K, lda, ldb, ldc, alpha,
                           blockIdx.y * BM, blockIdx.x * BN);
}

__global__ void __launch_bounds__(256, 2)
k_scores(const float* __restrict__ q, const float* __restrict__ kb,
         float* __restrict__ attn)
{
    int z = blockIdx.z;
    int b = z >> 3, h = z & 7;
    const float* A  = q  + (long)b * N_PEP * INNER + h * DH;
    const float* Bm = kb + (long)b * M_PRO * INNER + h * DH;
    float* C = attn + (long)z * N_PEP * M_PRO;
    gemm_mma<false, true>(A, Bm, C, N_PEP, M_PRO, DH,
                          INNER, INNER, M_PRO, SCALE_F,
                          blockIdx.y * BM, blockIdx.x * BN);
}

__global__ void __launch_bounds__(256, 2)
k_ctxprot(const float* __restrict__ attn, const float* __restrict__ vprot,
          float* __restrict__ ctx)
{
    int z = blockIdx.z; int b = z >> 3, h = z & 7;
    const float* A  = attn  + (long)z * N_PEP * M_PRO;
    const float* Bm = vprot + (long)b * M_PRO * INNER + h * DH;
    float* C = ctx + (long)b * N_PEP * INNER + h * DH;
    gemm_mma<false, false>(A, Bm, C, N_PEP, DH, M_PRO,
                           M_PRO, INNER, INNER, 1.0f, 0, 0);
}

__global__ void __launch_bounds__(256, 2)
k_ctxpep(const float* __restrict__ attn, const float* __restrict__ vpep,
         float* __restrict__ ctx)
{
    int z = blockIdx.z; int b = z >> 3, h = z & 7;
    const float* A  = attn + (long)z * N_PEP * M_PRO;   // (K=n, M=m) layout
    const float* Bm = vpep + (long)b * N_PEP * INNER + h * DH;
    float* C = ctx + (long)b * M_PRO * INNER + h * DH;
    gemm_mma<true, false>(A, Bm, C, M_PRO, DH, N_PEP,
                          M_PRO, INNER, INNER, 1.0f,
                          blockIdx.y * BM, 0);
}

// masked softmax over m, in-place on attn region of d_out
__global__ void __launch_bounds__(256)
k_softmax(float* __restrict__ attn, const int* __restrict__ pmask,
          const int* __restrict__ promask)
{
    int row = blockIdx.x;
    int n = row & (N_PEP - 1);
    int z = row / N_PEP;
    int b = z >> 3;
    float* p = attn + (long)row * M_PRO;
    const int row_valid = pmask[b * N_PEP + n];
    const int* pm = promask + b * M_PRO;
    const int tid = threadIdx.x;

    float vals[8];
    float mx = -INFINITY;
#pragma unroll
    for (int i = 0; i < 8; i++) {
        int c = tid + i * 256;
        float v = p[c];
        if (row_valid == 0 || pm[c] == 0) v = NEG_F;
        vals[i] = v;
        mx = fmaxf(mx, v);
    }
    __shared__ float red[256];
    red[tid] = mx; __syncthreads();
    for (int s = 128; s > 0; s >>= 1) {
        if (tid < s) red[tid] = fmaxf(red[tid], red[tid + s]);
        __syncthreads();
    }
    mx = red[0]; __syncthreads();

    float sum = 0.0f;
#pragma unroll
    for (int i = 0; i < 8; i++) { vals[i] = expf(vals[i] - mx); sum += vals[i]; }
    red[tid] = sum; __syncthreads();
    for (int s = 128; s > 0; s >>= 1) {
        if (tid < s) red[tid] += red[tid + s];
        __syncthreads();
    }
    float inv = 1.0f / red[0];
#pragma unroll
    for (int i = 0; i < 8; i++) p[tid + i * 256] = vals[i] * inv;
}

// out = LayerNorm(Y + bias + residual) * g + b
__global__ void __launch_bounds__(256)
k_ln(const float* __restrict__ Y, const float* __restrict__ bo,
     const float* __restrict__ resid, const float* __restrict__ g,
     const float* __restrict__ beta, float* __restrict__ out)
{
    int row = blockIdx.x;
    int tid = threadIdx.x;
    const float* y = Y + (long)row * INNER;
    const float* r = resid + (long)row * INNER;

    float x[3];
    float s = 0.0f;
#pragma unroll
    for (int i = 0; i < 3; i++) {
        int c = tid + i * 256;
        x[i] = y[c] + bo[c] + r[c];
        s += x[i];
    }
    __shared__ float red[256];
    red[tid] = s; __syncthreads();
    for (int st = 128; st > 0; st >>= 1) {
        if (tid < st) red[tid] += red[tid + st];
        __syncthreads();
    }
    float mu = red[0] * (1.0f / INNER); __syncthreads();

    float v = 0.0f;
#pragma unroll
    for (int i = 0; i < 3; i++) { float d = x[i] - mu; v += d * d; }
    red[tid] = v; __syncthreads();
    for (int st = 128; st > 0; st >>= 1) {
        if (tid < st) red[tid] += red[tid + st];
        __syncthreads();
    }
    float rstd = rsqrtf(red[0] * (1.0f / INNER) + EPS_F);
#pragma unroll
    for (int i = 0; i < 3; i++) {
        int c = tid + i * 256;
        out[(long)row * INNER + c] = (x[i] - mu) * rstd * g[c] + beta[c];
    }
}

// ---------------- launch ----------------
extern "C" void kernel_launch(void* const* d_in, const int* in_sizes, int n_in,
                              void* d_out, int out_size)
{
    const float* peptide = (const float*)d_in[0];
    const float* protein = (const float*)d_in[1];
    const int*   pmask   = (const int*)  d_in[2];
    const int*   promask = (const int*)  d_in[3];
    const float* Wq      = (const float*)d_in[4];
    const float* Wk      = (const float*)d_in[5];
    const float* Wvp     = (const float*)d_in[6];
    const float* Wvq     = (const float*)d_in[7];
    const float* Wop     = (const float*)d_in[8];
    const float* bop     = (const float*)d_in[9];
    const float* Woq     = (const float*)d_in[10];
    const float* boq     = (const float*)d_in[11];
    const float* lng     = (const float*)d_in[12];
    const float* lnb     = (const float*)d_in[13];

    float* out = (float*)d_out;
    float* out_prot = out;                                   // (16,128,768)
    float* out_pep  = out + (long)BATCH * N_PEP * INNER;     // (16,2048,768)
    float* attn     = out_pep + (long)BATCH * M_PRO * INNER; // (16,8,128,2048)

    float *q, *k, *vp, *vq, *cp, *cq, *y1, *y2;
    cudaGetSymbolAddress((void**)&q,  g_q);
    cudaGetSymbolAddress((void**)&k,  g_k);
    cudaGetSymbolAddress((void**)&vp, g_vp);
    cudaGetSymbolAddress((void**)&vq, g_vq);
    cudaGetSymbolAddress((void**)&cp, g_cp);
    cudaGetSymbolAddress((void**)&cq, g_cq);
    cudaGetSymbolAddress((void**)&y1, g_y1);
    cudaGetSymbolAddress((void**)&y2, g_y2);

    const dim3 blk(256);

    // projections
    k_gemm_nn<<<dim3(6, 16),  blk>>>(peptide, Wq,  q,  BATCH * N_PEP, INNER, INNER, INNER, INNER, INNER, 1.0f);
    k_gemm_nn<<<dim3(6, 16),  blk>>>(peptide, Wvq, vq, BATCH * N_PEP, INNER, INNER, INNER, INNER, INNER, 1.0f);
    k_gemm_nn<<<dim3(6, 256), blk>>>(protein, Wk,  k,  BATCH * M_PRO, INNER, INNER, INNER, INNER, INNER, 1.0f);
    k_gemm_nn<<<dim3(6, 256), blk>>>(protein, Wvp, vp, BATCH * M_PRO, INNER, INNER, INNER, INNER, INNER, 1.0f);

    // attention scores + softmax (attn lives in d_out)
    k_scores <<<dim3(16, 1, BATCH * HEADS), blk>>>(q, k, attn);
    k_softmax<<<BATCH * HEADS * N_PEP, 256>>>(attn, pmask, promask);

    // context
    k_ctxprot<<<dim3(1, 1,  BATCH * HEADS), blk>>>(attn, vp, cp);
    k_ctxpep <<<dim3(1, 16, BATCH * HEADS), blk>>>(attn, vq, cq);

    // output projections
    k_gemm_nn<<<dim3(6, 16),  blk>>>(cp, Wop, y1, BATCH * N_PEP, INNER, INNER, INNER, INNER, INNER, 1.0f);
    k_gemm_nn<<<dim3(6, 256), blk>>>(cq, Woq, y2, BATCH * M_PRO, INNER, INNER, INNER, INNER, INNER, 1.0f);

    // bias + residual + layernorm
    k_ln<<<BATCH * N_PEP, 256>>>(y1, bop, peptide, lng, lnb, out_prot);
    k_ln<<<BATCH * M_PRO, 256>>>(y2, boq, protein, lng, lnb, out_pep);
}

// round 8
// speedup vs baseline: 2.0090x; 1.2858x over previous
#include <cuda_runtime.h>
#include <math.h>

#define BATCH   16
#define N_PEP   128
#define M_PRO   2048
#define HEADS   8
#define DH      96
#define INNER   768
#define SCALE_F 0.10206207261596577f   /* 96^-0.5 */
#define NEG_F   -1000000.0f
#define EPS_F   1e-5f

#define BM 128
#define BN 128
#define BK 16
#define TILE_W 2048        /* words per operand tile (128x16 or 16x128) */
#define STAGES 3

// ---------------- scratch (device globals; no allocations) ----------------
__device__ float g_q   [BATCH * N_PEP * INNER];
__device__ float g_k   [BATCH * M_PRO * INNER];
__device__ float g_vp  [BATCH * M_PRO * INNER];
__device__ float g_vq  [BATCH * N_PEP * INNER];
__device__ float g_cp  [BATCH * N_PEP * INNER];
__device__ float g_cq  [BATCH * M_PRO * INNER];
__device__ float g_y1  [BATCH * N_PEP * INNER];
__device__ float g_y2  [BATCH * M_PRO * INNER];

// ---------------- helpers ----------------
__device__ __forceinline__ void mma_tf32(float* c, const unsigned* a,
                                         unsigned b0, unsigned b1) {
    asm volatile(
        "mma.sync.aligned.m16n8k8.row.col.f32.tf32.tf32.f32 "
        "{%0,%1,%2,%3}, {%4,%5,%6,%7}, {%8,%9}, {%0,%1,%2,%3};"
        : "+f"(c[0]), "+f"(c[1]), "+f"(c[2]), "+f"(c[3])
        : "r"(a[0]), "r"(a[1]), "r"(a[2]), "r"(a[3]), "r"(b0), "r"(b1));
}

__device__ __forceinline__ void cpasync16(unsigned* dst, const float* src, bool pred) {
    unsigned sa = (unsigned)__cvta_generic_to_shared(dst);
    int sz = pred ? 16 : 0;
    asm volatile("cp.async.cg.shared.global [%0], [%1], 16, %2;\n"
                 :: "r"(sa), "l"(src), "r"(sz));
}
#define CP_COMMIT() asm volatile("cp.async.commit_group;\n" ::)
#define CP_WAIT1()  asm volatile("cp.async.wait_group 1;\n" ::)
#define CP_WAIT0()  asm volatile("cp.async.wait_group 0;\n" ::)

// swizzled word layouts, zero padding, all accesses conflict-free:
//   16-word rows (A[m][k], B[n][k]):   r*16  + (c ^ (((r>>1)&3)*4))
//   128-word rows (A[k][m], B[k][n]):  r*128 + (c ^ ((r&7)*8))
#define SW16(r, c)  ((r) * 16  + ((c) ^ ((((r) >> 1) & 3) * 4)))
#define SW128(r, c) ((r) * 128 + ((c) ^ (((r) & 7) * 8)))

// ---------------- 128x128x16 3-stage-pipelined tf32 GEMM tile ----------------
// Raw fp32 bits are fed to mma.sync.tf32 (HW truncates to tf32).
// TA: A stored (K, M) row-major, lda; else (M, K).
// TB: B stored (N, K) row-major, ldb; else (K, N).
// K % 16 == 0; M covered exactly by grid; N % 4 == 0.
template <bool TA, bool TB>
__device__ __forceinline__ void gemm_mma(const float* __restrict__ A,
                                         const float* __restrict__ Bm,
                                         float* __restrict__ C,
                                         int M, int N, int K,
                                         int lda, int ldb, int ldc,
                                         float alpha, int row0, int col0)
{
    __shared__ unsigned sAb[STAGES][TILE_W];
    __shared__ unsigned sBb[STAGES][TILE_W];

    const int tid  = threadIdx.x;
    const int lane = tid & 31;
    const int wid  = tid >> 5;
    const int wm   = (wid >> 1) * 32;
    const int wn   = (wid & 1) * 64;

    float acc[2][8][4];
#pragma unroll
    for (int i = 0; i < 2; i++)
#pragma unroll
        for (int j = 0; j < 8; j++)
#pragma unroll
            for (int t = 0; t < 4; t++) acc[i][j][t] = 0.0f;

    const int nTiles = K / BK;

    // ---- async copy one k-tile into stage buffer ----
    auto issue = [&](int buf, int k0) {
        unsigned* sA = sAb[buf];
        unsigned* sB = sBb[buf];
#pragma unroll
        for (int it = 0; it < 2; it++) {
            int idx = tid + it * 256;          // 0..511
            if (!TA) {
                int m  = idx >> 2;             // 0..127
                int kk = (idx & 3) * 4;        // 0,4,8,12
                cpasync16(&sA[SW16(m, kk)],
                          &A[(long)(row0 + m) * lda + k0 + kk], true);
            } else {
                int kk = idx >> 5;             // 0..15
                int m4 = (idx & 31) * 4;       // 0..124
                cpasync16(&sA[SW128(kk, m4)],
                          &A[(long)(k0 + kk) * lda + row0 + m4], true);
            }
        }
#pragma unroll
        for (int it = 0; it < 2; it++) {
            int idx = tid + it * 256;
            if (!TB) {
                int kk = idx >> 5;
                int n4 = (idx & 31) * 4;
                cpasync16(&sB[SW128(kk, n4)],
                          &Bm[(long)(k0 + kk) * ldb + col0 + n4],
                          col0 + n4 < N);
            } else {
                int n  = idx >> 2;
                int kq = (idx & 3) * 4;
                cpasync16(&sB[SW16(n, kq)],
                          &Bm[(long)(col0 + n) * ldb + k0 + kq],
                          col0 + n < N);
            }
        }
        CP_COMMIT();
    };

    const int arq = lane >> 2;      // 0..7
    const int ac  = lane & 3;       // 0..3

    issue(0, 0);
    if (nTiles > 1) issue(1, BK);

    for (int t = 0; t < nTiles; t++) {
        const int buf = t % STAGES;
        unsigned* sA = sAb[buf];
        unsigned* sB = sBb[buf];

        // tile t complete (pending groups: t, t+1 -> leave <=1)
        if (t + 1 < nTiles) CP_WAIT1(); else CP_WAIT0();
        __syncthreads();               // publishes tile t; all warps past mma t-1
        if (t + 2 < nTiles) issue((t + 2) % STAGES, (t + 2) * BK);

#pragma unroll
        for (int kc = 0; kc < BK; kc += 8) {
            unsigned af0[4], af1[4];
            if (!TA) {
                af0[0] = sA[SW16(wm + arq,      kc + ac)];
                af0[1] = sA[SW16(wm + arq + 8,  kc + ac)];
                af0[2] = sA[SW16(wm + arq,      kc + ac + 4)];
                af0[3] = sA[SW16(wm + arq + 8,  kc + ac + 4)];
                af1[0] = sA[SW16(wm + arq + 16, kc + ac)];
                af1[1] = sA[SW16(wm + arq + 24, kc + ac)];
                af1[2] = sA[SW16(wm + arq + 16, kc + ac + 4)];
                af1[3] = sA[SW16(wm + arq + 24, kc + ac + 4)];
            } else {
                af0[0] = sA[SW128(kc + ac,     wm + arq)];
                af0[1] = sA[SW128(kc + ac,     wm + arq + 8)];
                af0[2] = sA[SW128(kc + ac + 4, wm + arq)];
                af0[3] = sA[SW128(kc + ac + 4, wm + arq + 8)];
                af1[0] = sA[SW128(kc + ac,     wm + arq + 16)];
                af1[1] = sA[SW128(kc + ac,     wm + arq + 24)];
                af1[2] = sA[SW128(kc + ac + 4, wm + arq + 16)];
                af1[3] = sA[SW128(kc + ac + 4, wm + arq + 24)];
            }
#pragma unroll
            for (int j = 0; j < 8; j++) {
                const int bn = wn + j * 8 + arq;
                unsigned b0, b1;
                if (!TB) {
                    b0 = sB[SW128(kc + ac,     bn)];
                    b1 = sB[SW128(kc + ac + 4, bn)];
                } else {
                    b0 = sB[SW16(bn, kc + ac)];
                    b1 = sB[SW16(bn, kc + ac + 4)];
                }
                mma_tf32(acc[0][j], af0, b0, b1);
                mma_tf32(acc[1][j], af1, b0, b1);
            }
        }
    }

    // ---- epilogue ----
#pragma unroll
    for (int i = 0; i < 2; i++) {
#pragma unroll
        for (int j = 0; j < 8; j++) {
            int r = row0 + wm + i * 16 + arq;
            int c = col0 + wn + j * 8 + ac * 2;
            if (c < N) {
                *(float2*)&C[(long)r * ldc + c] =
                    make_float2(alpha * acc[i][j][0], alpha * acc[i][j][1]);
                *(float2*)&C[(long)(r + 8) * ldc + c] =
                    make_float2(alpha * acc[i][j][2], alpha * acc[i][j][3]);
            }
        }
    }
}

// ---------------- kernel wrappers ----------------
__global__ void __launch_bounds__(256, 2)
k_gemm_nn(const float* __restrict__ A, const float* __restrict__ Bm,
          float* __restrict__ C, int M, int N, int K,
          int lda, int ldb, int ldc, float alpha)
{
    gemm_mma<false, false>(A, Bm, C, M, N, K, lda, ldb, ldc, alpha,
                           blockIdx.y * BM, blockIdx.x * BN);
}

__global__ void __launch_bounds__(256, 2)
k_scores(const float* __restrict__ q, const float* __restrict__ kb,
         float* __restrict__ attn)
{
    int z = blockIdx.z;
    int b = z >> 3, h = z & 7;
    const float* A  = q  + (long)b * N_PEP * INNER + h * DH;
    const float* Bm = kb + (long)b * M_PRO * INNER + h * DH;
    float* C = attn + (long)z * N_PEP * M_PRO;
    gemm_mma<false, true>(A, Bm, C, N_PEP, M_PRO, DH,
                          INNER, INNER, M_PRO, SCALE_F,
                          blockIdx.y * BM, blockIdx.x * BN);
}

__global__ void __launch_bounds__(256, 2)
k_ctxprot(const float* __restrict__ attn, const float* __restrict__ vprot,
          float* __restrict__ ctx)
{
    int z = blockIdx.z; int b = z >> 3, h = z & 7;
    const float* A  = attn  + (long)z * N_PEP * M_PRO;
    const float* Bm = vprot + (long)b * M_PRO * INNER + h * DH;
    float* C = ctx + (long)b * N_PEP * INNER + h * DH;
    gemm_mma<false, false>(A, Bm, C, N_PEP, DH, M_PRO,
                           M_PRO, INNER, INNER, 1.0f, 0, 0);
}

__global__ void __launch_bounds__(256, 2)
k_ctxpep(const float* __restrict__ attn, const float* __restrict__ vpep,
         float* __restrict__ ctx)
{
    int z = blockIdx.z; int b = z >> 3, h = z & 7;
    const float* A  = attn + (long)z * N_PEP * M_PRO;   // (K=n, M=m) layout
    const float* Bm = vpep + (long)b * N_PEP * INNER + h * DH;
    float* C = ctx + (long)b * M_PRO * INNER + h * DH;
    gemm_mma<true, false>(A, Bm, C, M_PRO, DH, N_PEP,
                          M_PRO, INNER, INNER, 1.0f,
                          blockIdx.y * BM, 0);
}

// masked softmax over m, in-place on attn region of d_out
__global__ void __launch_bounds__(256)
k_softmax(float* __restrict__ attn, const int* __restrict__ pmask,
          const int* __restrict__ promask)
{
    int row = blockIdx.x;
    int n = row & (N_PEP - 1);
    int z = row / N_PEP;
    int b = z >> 3;
    float* p = attn + (long)row * M_PRO;
    const int row_valid = pmask[b * N_PEP + n];
    const int* pm = promask + b * M_PRO;
    const int tid = threadIdx.x;

    float vals[8];
    float mx = -INFINITY;
#pragma unroll
    for (int i = 0; i < 8; i++) {
        int c = tid + i * 256;
        float v = p[c];
        if (row_valid == 0 || pm[c] == 0) v = NEG_F;
        vals[i] = v;
        mx = fmaxf(mx, v);
    }
    __shared__ float red[256];
    red[tid] = mx; __syncthreads();
    for (int s = 128; s > 0; s >>= 1) {
        if (tid < s) red[tid] = fmaxf(red[tid], red[tid + s]);
        __syncthreads();
    }
    mx = red[0]; __syncthreads();

    float sum = 0.0f;
#pragma unroll
    for (int i = 0; i < 8; i++) { vals[i] = expf(vals[i] - mx); sum += vals[i]; }
    red[tid] = sum; __syncthreads();
    for (int s = 128; s > 0; s >>= 1) {
        if (tid < s) red[tid] += red[tid + s];
        __syncthreads();
    }
    float inv = 1.0f / red[0];
#pragma unroll
    for (int i = 0; i < 8; i++) p[tid + i * 256] = vals[i] * inv;
}

// out = LayerNorm(Y + bias + residual) * g + b
__global__ void __launch_bounds__(256)
k_ln(const float* __restrict__ Y, const float* __restrict__ bo,
     const float* __restrict__ resid, const float* __restrict__ g,
     const float* __restrict__ beta, float* __restrict__ out)
{
    int row = blockIdx.x;
    int tid = threadIdx.x;
    const float* y = Y + (long)row * INNER;
    const float* r = resid + (long)row * INNER;

    float x[3];
    float s = 0.0f;
#pragma unroll
    for (int i = 0; i < 3; i++) {
        int c = tid + i * 256;
        x[i] = y[c] + bo[c] + r[c];
        s += x[i];
    }
    __shared__ float red[256];
    red[tid] = s; __syncthreads();
    for (int st = 128; st > 0; st >>= 1) {
        if (tid < st) red[tid] += red[tid + st];
        __syncthreads();
    }
    float mu = red[0] * (1.0f / INNER); __syncthreads();

    float v = 0.0f;
#pragma unroll
    for (int i = 0; i < 3; i++) { float d = x[i] - mu; v += d * d; }
    red[tid] = v; __syncthreads();
    for (int st = 128; st > 0; st >>= 1) {
        if (tid < st) red[tid] += red[tid + st];
        __syncthreads();
    }
    float rstd = rsqrtf(red[0] * (1.0f / INNER) + EPS_F);
#pragma unroll
    for (int i = 0; i < 3; i++) {
        int c = tid + i * 256;
        out[(long)row * INNER + c] = (x[i] - mu) * rstd * g[c] + beta[c];
    }
}

// ---------------- launch ----------------
extern "C" void kernel_launch(void* const* d_in, const int* in_sizes, int n_in,
                              void* d_out, int out_size)
{
    const float* peptide = (const float*)d_in[0];
    const float* protein = (const float*)d_in[1];
    const int*   pmask   = (const int*)  d_in[2];
    const int*   promask = (const int*)  d_in[3];
    const float* Wq      = (const float*)d_in[4];
    const float* Wk      = (const float*)d_in[5];
    const float* Wvp     = (const float*)d_in[6];
    const float* Wvq     = (const float*)d_in[7];
    const float* Wop     = (const float*)d_in[8];
    const float* bop     = (const float*)d_in[9];
    const float* Woq     = (const float*)d_in[10];
    const float* boq     = (const float*)d_in[11];
    const float* lng     = (const float*)d_in[12];
    const float* lnb     = (const float*)d_in[13];

    float* out = (float*)d_out;
    float* out_prot = out;                                   // (16,128,768)
    float* out_pep  = out + (long)BATCH * N_PEP * INNER;     // (16,2048,768)
    float* attn     = out_pep + (long)BATCH * M_PRO * INNER; // (16,8,128,2048)

    float *q, *k, *vp, *vq, *cp, *cq, *y1, *y2;
    cudaGetSymbolAddress((void**)&q,  g_q);
    cudaGetSymbolAddress((void**)&k,  g_k);
    cudaGetSymbolAddress((void**)&vp, g_vp);
    cudaGetSymbolAddress((void**)&vq, g_vq);
    cudaGetSymbolAddress((void**)&cp, g_cp);
    cudaGetSymbolAddress((void**)&cq, g_cq);
    cudaGetSymbolAddress((void**)&y1, g_y1);
    cudaGetSymbolAddress((void**)&y2, g_y2);

    const dim3 blk(256);

    // projections
    k_gemm_nn<<<dim3(6, 16),  blk>>>(peptide, Wq,  q,  BATCH * N_PEP, INNER, INNER, INNER, INNER, INNER, 1.0f);
    k_gemm_nn<<<dim3(6, 16),  blk>>>(peptide, Wvq, vq, BATCH * N_PEP, INNER, INNER, INNER, INNER, INNER, 1.0f);
    k_gemm_nn<<<dim3(6, 256), blk>>>(protein, Wk,  k,  BATCH * M_PRO, INNER, INNER, INNER, INNER, INNER, 1.0f);
    k_gemm_nn<<<dim3(6, 256), blk>>>(protein, Wvp, vp, BATCH * M_PRO, INNER, INNER, INNER, INNER, INNER, 1.0f);

    // attention scores + softmax (attn lives in d_out)
    k_scores <<<dim3(16, 1, BATCH * HEADS), blk>>>(q, k, attn);
    k_softmax<<<BATCH * HEADS * N_PEP, 256>>>(attn, pmask, promask);

    // context
    k_ctxprot<<<dim3(1, 1,  BATCH * HEADS), blk>>>(attn, vp, cp);
    k_ctxpep <<<dim3(1, 16, BATCH * HEADS), blk>>>(attn, vq, cq);

    // output projections
    k_gemm_nn<<<dim3(6, 16),  blk>>>(cp, Wop, y1, BATCH * N_PEP, INNER, INNER, INNER, INNER, INNER, 1.0f);
    k_gemm_nn<<<dim3(6, 256), blk>>>(cq, Woq, y2, BATCH * M_PRO, INNER, INNER, INNER, INNER, INNER, 1.0f);

    // bias + residual + layernorm
    k_ln<<<BATCH * N_PEP, 256>>>(y1, bop, peptide, lng, lnb, out_prot);
    k_ln<<<BATCH * M_PRO, 256>>>(y2, boq, protein, lng, lnb, out_pep);
}

// round 9
// speedup vs baseline: 2.0696x; 1.0302x over previous
#include <cuda_runtime.h>
#include <math.h>

#define BATCH   16
#define N_PEP   128
#define M_PRO   2048
#define HEADS   8
#define DH      96
#define INNER   768
#define SCALE_F 0.10206207261596577f   /* 96^-0.5 */
#define NEG_F   -1000000.0f
#define EPS_F   1e-5f

#define BM 128
#define BN 128
#define BK 16
#define TILE_W 2048        /* words per operand tile (128x16 or 16x128) */
#define STAGES 3
#define KSPLIT 4
#define KCHUNK (M_PRO / KSPLIT)   /* 512 */

// ---------------- scratch (device globals; no allocations) ----------------
__device__ float g_q   [BATCH * N_PEP * INNER];
__device__ float g_k   [BATCH * M_PRO * INNER];
__device__ float g_vp  [BATCH * M_PRO * INNER];
__device__ float g_vq  [BATCH * N_PEP * INNER];
__device__ float g_cp  [BATCH * N_PEP * INNER];
__device__ float g_cq  [BATCH * M_PRO * INNER];
__device__ float g_y1  [BATCH * N_PEP * INNER];
__device__ float g_y2  [BATCH * M_PRO * INNER];
__device__ float g_part[KSPLIT * BATCH * N_PEP * INNER];

// ---------------- helpers ----------------
__device__ __forceinline__ void mma_tf32(float* c, const unsigned* a,
                                         unsigned b0, unsigned b1) {
    asm volatile(
        "mma.sync.aligned.m16n8k8.row.col.f32.tf32.tf32.f32 "
        "{%0,%1,%2,%3}, {%4,%5,%6,%7}, {%8,%9}, {%0,%1,%2,%3};"
        : "+f"(c[0]), "+f"(c[1]), "+f"(c[2]), "+f"(c[3])
        : "r"(a[0]), "r"(a[1]), "r"(a[2]), "r"(a[3]), "r"(b0), "r"(b1));
}

__device__ __forceinline__ void cpasync16(unsigned* dst, const float* src, bool pred) {
    unsigned sa = (unsigned)__cvta_generic_to_shared(dst);
    int sz = pred ? 16 : 0;
    asm volatile("cp.async.cg.shared.global [%0], [%1], 16, %2;\n"
                 :: "r"(sa), "l"(src), "r"(sz));
}
#define CP_COMMIT() asm volatile("cp.async.commit_group;\n" ::)
#define CP_WAIT1()  asm volatile("cp.async.wait_group 1;\n" ::)
#define CP_WAIT0()  asm volatile("cp.async.wait_group 0;\n" ::)

// swizzled word layouts, zero padding, all accesses conflict-free:
#define SW16(r, c)  ((r) * 16  + ((c) ^ ((((r) >> 1) & 3) * 4)))
#define SW128(r, c) ((r) * 128 + ((c) ^ (((r) & 7) * 8)))

// ---------------- 128x128x16 3-stage-pipelined tf32 GEMM tile ----------------
// Raw fp32 bits fed to mma.sync.tf32 (HW truncates).
// TA: A stored (K, M) row-major, lda; else (M, K).
// TB: B stored (N, K) row-major, ldb; else (K, N).
// MASK: apply attention masks in epilogue (C row = n index, col = m index).
template <bool TA, bool TB, bool MASK>
__device__ __forceinline__ void gemm_mma(const float* __restrict__ A,
                                         const float* __restrict__ Bm,
                                         float* __restrict__ C,
                                         int M, int N, int K,
                                         int lda, int ldb, int ldc,
                                         float alpha, int row0, int col0,
                                         const int* __restrict__ rowmask,
                                         const int* __restrict__ colmask)
{
    __shared__ unsigned sAb[STAGES][TILE_W];
    __shared__ unsigned sBb[STAGES][TILE_W];

    const int tid  = threadIdx.x;
    const int lane = tid & 31;
    const int wid  = tid >> 5;
    const int wm   = (wid >> 1) * 32;
    const int wn   = (wid & 1) * 64;

    float acc[2][8][4];
#pragma unroll
    for (int i = 0; i < 2; i++)
#pragma unroll
        for (int j = 0; j < 8; j++)
#pragma unroll
            for (int t = 0; t < 4; t++) acc[i][j][t] = 0.0f;

    const int nTiles = K / BK;

    auto issue = [&](int buf, int k0) {
        unsigned* sA = sAb[buf];
        unsigned* sB = sBb[buf];
#pragma unroll
        for (int it = 0; it < 2; it++) {
            int idx = tid + it * 256;
            if (!TA) {
                int m  = idx >> 2;
                int kk = (idx & 3) * 4;
                cpasync16(&sA[SW16(m, kk)],
                          &A[(long)(row0 + m) * lda + k0 + kk], true);
            } else {
                int kk = idx >> 5;
                int m4 = (idx & 31) * 4;
                cpasync16(&sA[SW128(kk, m4)],
                          &A[(long)(k0 + kk) * lda + row0 + m4], true);
            }
        }
#pragma unroll
        for (int it = 0; it < 2; it++) {
            int idx = tid + it * 256;
            if (!TB) {
                int kk = idx >> 5;
                int n4 = (idx & 31) * 4;
                cpasync16(&sB[SW128(kk, n4)],
                          &Bm[(long)(k0 + kk) * ldb + col0 + n4],
                          col0 + n4 < N);
            } else {
                int n  = idx >> 2;
                int kq = (idx & 3) * 4;
                cpasync16(&sB[SW16(n, kq)],
                          &Bm[(long)(col0 + n) * ldb + k0 + kq],
                          col0 + n < N);
            }
        }
        CP_COMMIT();
    };

    const int arq = lane >> 2;
    const int ac  = lane & 3;

    issue(0, 0);
    if (nTiles > 1) issue(1, BK);

    for (int t = 0; t < nTiles; t++) {
        const int buf = t % STAGES;
        unsigned* sA = sAb[buf];
        unsigned* sB = sBb[buf];

        if (t + 1 < nTiles) CP_WAIT1(); else CP_WAIT0();
        __syncthreads();
        if (t + 2 < nTiles) issue((t + 2) % STAGES, (t + 2) * BK);

#pragma unroll
        for (int kc = 0; kc < BK; kc += 8) {
            unsigned af0[4], af1[4];
            if (!TA) {
                af0[0] = sA[SW16(wm + arq,      kc + ac)];
                af0[1] = sA[SW16(wm + arq + 8,  kc + ac)];
                af0[2] = sA[SW16(wm + arq,      kc + ac + 4)];
                af0[3] = sA[SW16(wm + arq + 8,  kc + ac + 4)];
                af1[0] = sA[SW16(wm + arq + 16, kc + ac)];
                af1[1] = sA[SW16(wm + arq + 24, kc + ac)];
                af1[2] = sA[SW16(wm + arq + 16, kc + ac + 4)];
                af1[3] = sA[SW16(wm + arq + 24, kc + ac + 4)];
            } else {
                af0[0] = sA[SW128(kc + ac,     wm + arq)];
                af0[1] = sA[SW128(kc + ac,     wm + arq + 8)];
                af0[2] = sA[SW128(kc + ac + 4, wm + arq)];
                af0[3] = sA[SW128(kc + ac + 4, wm + arq + 8)];
                af1[0] = sA[SW128(kc + ac,     wm + arq + 16)];
                af1[1] = sA[SW128(kc + ac,     wm + arq + 24)];
                af1[2] = sA[SW128(kc + ac + 4, wm + arq + 16)];
                af1[3] = sA[SW128(kc + ac + 4, wm + arq + 24)];
            }
#pragma unroll
            for (int j = 0; j < 8; j++) {
                const int bn = wn + j * 8 + arq;
                unsigned b0, b1;
                if (!TB) {
                    b0 = sB[SW128(kc + ac,     bn)];
                    b1 = sB[SW128(kc + ac + 4, bn)];
                } else {
                    b0 = sB[SW16(bn, kc + ac)];
                    b1 = sB[SW16(bn, kc + ac + 4)];
                }
                mma_tf32(acc[0][j], af0, b0, b1);
                mma_tf32(acc[1][j], af1, b0, b1);
            }
        }
    }

    // ---- epilogue ----
#pragma unroll
    for (int i = 0; i < 2; i++) {
        int r  = row0 + wm + i * 16 + arq;
        int rv0 = 1, rv1 = 1;
        if (MASK) { rv0 = rowmask[r]; rv1 = rowmask[r + 8]; }
#pragma unroll
        for (int j = 0; j < 8; j++) {
            int c = col0 + wn + j * 8 + ac * 2;
            if (c < N) {
                float v0 = alpha * acc[i][j][0];
                float v1 = alpha * acc[i][j][1];
                float v2 = alpha * acc[i][j][2];
                float v3 = alpha * acc[i][j][3];
                if (MASK) {
                    int cm0 = colmask[c], cm1 = colmask[c + 1];
                    if (rv0 == 0 || cm0 == 0) v0 = NEG_F;
                    if (rv0 == 0 || cm1 == 0) v1 = NEG_F;
                    if (rv1 == 0 || cm0 == 0) v2 = NEG_F;
                    if (rv1 == 0 || cm1 == 0) v3 = NEG_F;
                }
                *(float2*)&C[(long)r * ldc + c]       = make_float2(v0, v1);
                *(float2*)&C[(long)(r + 8) * ldc + c] = make_float2(v2, v3);
            }
        }
    }
}

// ---------------- kernel wrappers ----------------
__global__ void __launch_bounds__(256, 2)
k_gemm_nn(const float* __restrict__ A, const float* __restrict__ Bm,
          float* __restrict__ C, int M, int N, int K,
          int lda, int ldb, int ldc, float alpha)
{
    gemm_mma<false, false, false>(A, Bm, C, M, N, K, lda, ldb, ldc, alpha,
                                  blockIdx.y * BM, blockIdx.x * BN, 0, 0);
}

// scores with fused masking: writes NEG_F where masked
__global__ void __launch_bounds__(256, 2)
k_scores(const float* __restrict__ q, const float* __restrict__ kb,
         float* __restrict__ attn,
         const int* __restrict__ pmask, const int* __restrict__ promask)
{
    int z = blockIdx.z;
    int b = z >> 3, h = z & 7;
    const float* A  = q  + (long)b * N_PEP * INNER + h * DH;
    const float* Bm = kb + (long)b * M_PRO * INNER + h * DH;
    float* C = attn + (long)z * N_PEP * M_PRO;
    gemm_mma<false, true, true>(A, Bm, C, N_PEP, M_PRO, DH,
                                INNER, INNER, M_PRO, SCALE_F,
                                blockIdx.y * BM, blockIdx.x * BN,
                                pmask + b * N_PEP, promask + b * M_PRO);
}

// split-K ctx_prot: z = bh * KSPLIT + chunk; partial C per chunk
__global__ void __launch_bounds__(256, 2)
k_ctxprot(const float* __restrict__ attn, const float* __restrict__ vprot,
          float* __restrict__ part)
{
    int z = blockIdx.z;
    int bh = z >> 2, chunk = z & 3;
    int b = bh >> 3, h = bh & 7;
    const float* A  = attn  + (long)bh * N_PEP * M_PRO + chunk * KCHUNK;
    const float* Bm = vprot + (long)b * M_PRO * INNER + (long)chunk * KCHUNK * INNER + h * DH;
    float* C = part + (long)chunk * (BATCH * N_PEP * INNER)
                    + (long)b * N_PEP * INNER + h * DH;
    gemm_mma<false, false, false>(A, Bm, C, N_PEP, DH, KCHUNK,
                                  M_PRO, INNER, INNER, 1.0f, 0, 0, 0, 0);
}

// reduce 4 partials -> cp
__global__ void __launch_bounds__(256)
k_reduce4(const float* __restrict__ part, float* __restrict__ cp)
{
    const long STRIDE = (long)BATCH * N_PEP * INNER;   // 1572864
    long i = ((long)blockIdx.x * 256 + threadIdx.x) * 4;
    if (i >= STRIDE) return;
    float4 a = *(const float4*)&part[i];
    float4 b = *(const float4*)&part[STRIDE + i];
    float4 c = *(const float4*)&part[2 * STRIDE + i];
    float4 d = *(const float4*)&part[3 * STRIDE + i];
    float4 r = make_float4(a.x + b.x + c.x + d.x, a.y + b.y + c.y + d.y,
                           a.z + b.z + c.z + d.z, a.w + b.w + c.w + d.w);
    *(float4*)&cp[i] = r;
}

__global__ void __launch_bounds__(256, 2)
k_ctxpep(const float* __restrict__ attn, const float* __restrict__ vpep,
         float* __restrict__ ctx)
{
    int z = blockIdx.z; int b = z >> 3, h = z & 7;
    const float* A  = attn + (long)z * N_PEP * M_PRO;
    const float* Bm = vpep + (long)b * N_PEP * INNER + h * DH;
    float* C = ctx + (long)b * M_PRO * INNER + h * DH;
    gemm_mma<true, false, false>(A, Bm, C, M_PRO, DH, N_PEP,
                                 M_PRO, INNER, INNER, 1.0f,
                                 blockIdx.y * BM, 0, 0, 0);
}

// ---------------- softmax (masks pre-applied as NEG_F) ----------------
__global__ void __launch_bounds__(256)
k_softmax(float* __restrict__ attn)
{
    const int tid = threadIdx.x;
    float* p = attn + (long)blockIdx.x * M_PRO;

    float4 v0 = *(float4*)&p[tid * 4];
    float4 v1 = *(float4*)&p[1024 + tid * 4];

    float mx = fmaxf(fmaxf(fmaxf(v0.x, v0.y), fmaxf(v0.z, v0.w)),
                     fmaxf(fmaxf(v1.x, v1.y), fmaxf(v1.z, v1.w)));
#pragma unroll
    for (int o = 16; o; o >>= 1)
        mx = fmaxf(mx, __shfl_xor_sync(0xffffffff, mx, o));
    __shared__ float red[8];
    if ((tid & 31) == 0) red[tid >> 5] = mx;
    __syncthreads();
    if (tid < 8) {
        float m = red[tid];
#pragma unroll
        for (int o = 4; o; o >>= 1) m = fmaxf(m, __shfl_xor_sync(0xff, m, o));
        red[tid] = m;
    }
    __syncthreads();
    mx = red[0];

    v0.x = expf(v0.x - mx); v0.y = expf(v0.y - mx);
    v0.z = expf(v0.z - mx); v0.w = expf(v0.w - mx);
    v1.x = expf(v1.x - mx); v1.y = expf(v1.y - mx);
    v1.z = expf(v1.z - mx); v1.w = expf(v1.w - mx);
    float s = v0.x + v0.y + v0.z + v0.w + v1.x + v1.y + v1.z + v1.w;
#pragma unroll
    for (int o = 16; o; o >>= 1) s += __shfl_xor_sync(0xffffffff, s, o);
    __shared__ float red2[8];
    if ((tid & 31) == 0) red2[tid >> 5] = s;
    __syncthreads();
    if (tid < 8) {
        float t = red2[tid];
#pragma unroll
        for (int o = 4; o; o >>= 1) t += __shfl_xor_sync(0xff, t, o);
        red2[tid] = t;
    }
    __syncthreads();
    float inv = 1.0f / red2[0];

    v0.x *= inv; v0.y *= inv; v0.z *= inv; v0.w *= inv;
    v1.x *= inv; v1.y *= inv; v1.z *= inv; v1.w *= inv;
    *(float4*)&p[tid * 4] = v0;
    *(float4*)&p[1024 + tid * 4] = v1;
}

// ---------------- out = LayerNorm(Y + bias + residual) * g + b ----------------
__global__ void __launch_bounds__(256)
k_ln(const float* __restrict__ Y, const float* __restrict__ bo,
     const float* __restrict__ resid, const float* __restrict__ g,
     const float* __restrict__ beta, float* __restrict__ out)
{
    int row = blockIdx.x;
    int tid = threadIdx.x;
    const float* y = Y + (long)row * INNER;
    const float* r = resid + (long)row * INNER;

    float x[3];
    float s = 0.0f;
#pragma unroll
    for (int i = 0; i < 3; i++) {
        int c = tid + i * 256;
        x[i] = y[c] + bo[c] + r[c];
        s += x[i];
    }
#pragma unroll
    for (int o = 16; o; o >>= 1) s += __shfl_xor_sync(0xffffffff, s, o);
    __shared__ float red[8];
    if ((tid & 31) == 0) red[tid >> 5] = s;
    __syncthreads();
    if (tid < 8) {
        float t = red[tid];
#pragma unroll
        for (int o = 4; o; o >>= 1) t += __shfl_xor_sync(0xff, t, o);
        red[tid] = t;
    }
    __syncthreads();
    float mu = red[0] * (1.0f / INNER);

    float v = 0.0f;
#pragma unroll
    for (int i = 0; i < 3; i++) { float d = x[i] - mu; v += d * d; }
#pragma unroll
    for (int o = 16; o; o >>= 1) v += __shfl_xor_sync(0xffffffff, v, o);
    __shared__ float red2[8];
    if ((tid & 31) == 0) red2[tid >> 5] = v;
    __syncthreads();
    if (tid < 8) {
        float t = red2[tid];
#pragma unroll
        for (int o = 4; o; o >>= 1) t += __shfl_xor_sync(0xff, t, o);
        red2[tid] = t;
    }
    __syncthreads();
    float rstd = rsqrtf(red2[0] * (1.0f / INNER) + EPS_F);
#pragma unroll
    for (int i = 0; i < 3; i++) {
        int c = tid + i * 256;
        out[(long)row * INNER + c] = (x[i] - mu) * rstd * g[c] + beta[c];
    }
}

// ---------------- launch ----------------
extern "C" void kernel_launch(void* const* d_in, const int* in_sizes, int n_in,
                              void* d_out, int out_size)
{
    const float* peptide = (const float*)d_in[0];
    const float* protein = (const float*)d_in[1];
    const int*   pmask   = (const int*)  d_in[2];
    const int*   promask = (const int*)  d_in[3];
    const float* Wq      = (const float*)d_in[4];
    const float* Wk      = (const float*)d_in[5];
    const float* Wvp     = (const float*)d_in[6];
    const float* Wvq     = (const float*)d_in[7];
    const float* Wop     = (const float*)d_in[8];
    const float* bop     = (const float*)d_in[9];
    const float* Woq     = (const float*)d_in[10];
    const float* boq     = (const float*)d_in[11];
    const float* lng     = (const float*)d_in[12];
    const float* lnb     = (const float*)d_in[13];

    float* out = (float*)d_out;
    float* out_prot = out;                                   // (16,128,768)
    float* out_pep  = out + (long)BATCH * N_PEP * INNER;     // (16,2048,768)
    float* attn     = out_pep + (long)BATCH * M_PRO * INNER; // (16,8,128,2048)

    float *q, *k, *vp, *vq, *cp, *cq, *y1, *y2, *part;
    cudaGetSymbolAddress((void**)&q,  g_q);
    cudaGetSymbolAddress((void**)&k,  g_k);
    cudaGetSymbolAddress((void**)&vp, g_vp);
    cudaGetSymbolAddress((void**)&vq, g_vq);
    cudaGetSymbolAddress((void**)&cp, g_cp);
    cudaGetSymbolAddress((void**)&cq, g_cq);
    cudaGetSymbolAddress((void**)&y1, g_y1);
    cudaGetSymbolAddress((void**)&y2, g_y2);
    cudaGetSymbolAddress((void**)&part, g_part);

    const dim3 blk(256);

    // projections
    k_gemm_nn<<<dim3(6, 16),  blk>>>(peptide, Wq,  q,  BATCH * N_PEP, INNER, INNER, INNER, INNER, INNER, 1.0f);
    k_gemm_nn<<<dim3(6, 16),  blk>>>(peptide, Wvq, vq, BATCH * N_PEP, INNER, INNER, INNER, INNER, INNER, 1.0f);
    k_gemm_nn<<<dim3(6, 256), blk>>>(protein, Wk,  k,  BATCH * M_PRO, INNER, INNER, INNER, INNER, INNER, 1.0f);
    k_gemm_nn<<<dim3(6, 256), blk>>>(protein, Wvp, vp, BATCH * M_PRO, INNER, INNER, INNER, INNER, INNER, 1.0f);

    // attention scores (mask fused) + softmax (attn lives in d_out)
    k_scores <<<dim3(16, 1, BATCH * HEADS), blk>>>(q, k, attn, pmask, promask);
    k_softmax<<<BATCH * HEADS * N_PEP, 256>>>(attn);

    // context
    k_ctxprot<<<dim3(1, 1, BATCH * HEADS * KSPLIT), blk>>>(attn, vp, part);
    k_reduce4<<<(BATCH * N_PEP * INNER / 4 + 255) / 256, blk>>>(part, cp);
    k_ctxpep <<<dim3(1, 16, BATCH * HEADS), blk>>>(attn, vq, cq);

    // output projections
    k_gemm_nn<<<dim3(6, 16),  blk>>>(cp, Wop, y1, BATCH * N_PEP, INNER, INNER, INNER, INNER, INNER, 1.0f);
    k_gemm_nn<<<dim3(6, 256), blk>>>(cq, Woq, y2, BATCH * M_PRO, INNER, INNER, INNER, INNER, INNER, 1.0f);

    // bias + residual + layernorm
    k_ln<<<BATCH * N_PEP, 256>>>(y1, bop, peptide, lng, lnb, out_prot);
    k_ln<<<BATCH * M_PRO, 256>>>(y2, boq, protein, lng, lnb, out_pep);
}